// round 17
// baseline (speedup 1.0000x reference)
#include <cuda_runtime.h>
#include <cuda_fp16.h>
#include <cstdint>
#include <math.h>

// ---------------------------------------------------------------------------
// Problem dims (fixed)
// ---------------------------------------------------------------------------
#define SEQ   1024
#define BATCH 16
#define HDIM  1024
#define KDIM  1024
#define MDIM  (SEQ * BATCH)     // 16384
#define NDIM  (3 * HDIM)        // 3072

// ---------------------------------------------------------------------------
// Device scratch (static only). Gates stored as fp16 (activated values).
// ---------------------------------------------------------------------------
__device__ __half g_Z[(size_t)MDIM * HDIM];
__device__ __half g_F[(size_t)MDIM * HDIM];
__device__ __half g_O[(size_t)MDIM * HDIM];

__device__ __half g_Xh[(size_t)MDIM * KDIM];
__device__ __half g_Wh[(size_t)NDIM * KDIM];

#define NCHUNK 64
#define CLEN   16               // SEQ / NCHUNK
#define NCHAIN (BATCH * HDIM)   // 16384
#define NCG4   (NCHAIN / 4)     // 4096 chain-groups of 4
__device__ float g_cA[NCHUNK * NCHAIN];
__device__ float g_cB[NCHUNK * NCHAIN];
__device__ float g_cH[NCHUNK * NCHAIN];

// ---------------------------------------------------------------------------
// Helpers
// ---------------------------------------------------------------------------
// PDL: overlap launch fronts; wait() blocks until producer kernel completes,
// so data visibility is unchanged. No-ops if launched without the attribute.
#define GDC_LAUNCH() asm volatile("griddepcontrol.launch_dependents;" ::: "memory")
#define GDC_WAIT()   asm volatile("griddepcontrol.wait;" ::: "memory")

static __device__ __forceinline__ uint32_t smem_u32(const void* p) {
    uint32_t a;
    asm("{ .reg .u64 t; cvta.to.shared.u64 t, %1; cvt.u32.u64 %0, t; }"
        : "=r"(a) : "l"(p));
    return a;
}

static __device__ __forceinline__ void cp16(uint32_t saddr, const void* gaddr) {
    asm volatile("cp.async.cg.shared.global [%0], [%1], 16;"
                 :: "r"(saddr), "l"(gaddr) : "memory");
}
#define CP_COMMIT() asm volatile("cp.async.commit_group;" ::: "memory")
#define CP_WAIT1()  asm volatile("cp.async.wait_group 1;" ::: "memory")

static __device__ __forceinline__ void ldsm4(uint32_t* r, uint32_t addr) {
    asm volatile("ldmatrix.sync.aligned.m8n8.x4.shared.b16 {%0,%1,%2,%3}, [%4];"
                 : "=r"(r[0]), "=r"(r[1]), "=r"(r[2]), "=r"(r[3]) : "r"(addr));
}

static __device__ __forceinline__ void mma16816(float* d, const uint32_t* a,
                                                const uint32_t* b) {
    asm volatile(
        "mma.sync.aligned.m16n8k16.row.col.f32.f16.f16.f32 "
        "{%0,%1,%2,%3}, {%4,%5,%6,%7}, {%8,%9}, {%0,%1,%2,%3};"
        : "+f"(d[0]), "+f"(d[1]), "+f"(d[2]), "+f"(d[3])
        : "r"(a[0]), "r"(a[1]), "r"(a[2]), "r"(a[3]), "r"(b[0]), "r"(b[1]));
}

static __device__ __forceinline__ float fast_sigmoid(float y) {
    return 1.0f / (1.0f + __expf(-y));
}
static __device__ __forceinline__ float fast_tanh(float y) {
    return 2.0f / (1.0f + __expf(-2.0f * y)) - 1.0f;
}

// ---------------------------------------------------------------------------
// fp32 -> fp16 conversion prepass (X and W fused into one launch)
// ---------------------------------------------------------------------------
#define NX4 (MDIM * KDIM / 4)   // 4,194,304 float4 in X
#define NW4 (NDIM * KDIM / 4)   //   786,432 float4 in W

__global__ __launch_bounds__(256) void conv_kernel(
    const float4* __restrict__ X4, const float4* __restrict__ W4)
{
    GDC_LAUNCH();
    const int i = blockIdx.x * 256 + threadIdx.x;
    const bool isx = i < NX4;
    const float4 v = isx ? X4[i] : W4[i - NX4];
    __half2* dst = isx ? (__half2*)g_Xh : (__half2*)g_Wh;
    const int j = isx ? i : (i - NX4);
    dst[2 * j + 0] = __floats2half2_rn(v.x, v.y);
    dst[2 * j + 1] = __floats2half2_rn(v.z, v.w);
}

// ---------------------------------------------------------------------------
// HMMA GEMM (R9 config, best measured): 128x128 tile, BK=64, 256 threads,
// 3-stage cp.async, 2 CTAs/SM, warp tiling 4m x 2n.
// Y[m,n] = sum_k X[m,k]*W[n,k] + b[n]; fused bias+activation; fp16 gate store.
// smem rows are 64 fp16 = 128B; swizzle: 16B group g at row r -> g ^ (r&7).
// ---------------------------------------------------------------------------
#define BM 128
#define BN 128
#define BK 64
#define PLANE_BYTES (128 * 128)          // 16 KB
#define STAGE_BYTES (2 * PLANE_BYTES)    // 32 KB
#define NSTAGE 3
#define GEMM_SMEM (NSTAGE * STAGE_BYTES) // 96 KB -> 2 CTAs/SM
#define NCHK (KDIM / BK)                 // 16

#define OFF_A 0
#define OFF_B PLANE_BYTES

__global__ __launch_bounds__(256, 2) void gemm_hmma_kernel(
    const float* __restrict__ bias)
{
    extern __shared__ char sm[];
    const uint32_t sbase = smem_u32(sm);

    const int tid = threadIdx.x;
    const int wid = tid >> 5;
    const int lid = tid & 31;
    const int bm = blockIdx.y * BM;
    const int bn = blockIdx.x * BN;

    const int wm = wid >> 1;
    const int wn = wid & 1;

    float acc[2][8][4];
    #pragma unroll
    for (int i = 0; i < 2; i++)
        #pragma unroll
        for (int j = 0; j < 8; j++)
            #pragma unroll
            for (int q = 0; q < 4; q++)
                acc[i][j][q] = 0.0f;

    auto load_stage = [&](int c, int s) {
        const uint32_t sb = sbase + s * STAGE_BYTES;
        const int k0 = c * BK;
        #pragma unroll
        for (int i = 0; i < 4; i++) {
            const int u = tid + i * 256;          // 0..1023
            const int row = u >> 3;
            const int kg = u & 7;
            const uint32_t so = row * 128 + 16 * (kg ^ (row & 7));
            const size_t gx = ((size_t)(bm + row) * KDIM + k0 + kg * 8) * 2;
            const size_t gw = ((size_t)(bn + row) * KDIM + k0 + kg * 8) * 2;
            cp16(sb + OFF_A + so, (const char*)g_Xh + gx);
            cp16(sb + OFF_B + so, (const char*)g_Wh + gw);
        }
    };

    const int a_rl = lid & 15;
    const int a_kh = lid >> 4;
    const int b_rl = (lid & 7) + ((lid & 16) >> 1);
    const int b_kh = (lid >> 3) & 1;

    GDC_LAUNCH();
    GDC_WAIT();          // conv_kernel's g_Xh/g_Wh must be complete

    load_stage(0, 0); CP_COMMIT();
    load_stage(1, 1); CP_COMMIT();

    for (int c = 0; c < NCHK; c++) {
        CP_WAIT1();
        __syncthreads();
        if (c + 2 < NCHK) load_stage(c + 2, (c + 2) % NSTAGE);
        CP_COMMIT();

        const uint32_t sb = sbase + (c % NSTAGE) * STAGE_BYTES;

        #pragma unroll
        for (int kf = 0; kf < 4; kf++) {
            uint32_t a[2][4], b[8][2];

            #pragma unroll
            for (int mf = 0; mf < 2; mf++) {
                const int row = wm * 32 + mf * 16 + a_rl;
                const int kg = 2 * kf + a_kh;
                const uint32_t so = row * 128 + 16 * (kg ^ (row & 7));
                ldsm4(a[mf], sb + OFF_A + so);
            }
            #pragma unroll
            for (int nq = 0; nq < 4; nq++) {
                const int row = wn * 64 + nq * 16 + b_rl;
                const int kg = 2 * kf + b_kh;
                const uint32_t so = row * 128 + 16 * (kg ^ (row & 7));
                uint32_t t[4];
                ldsm4(t, sb + OFF_B + so);
                b[nq * 2][0] = t[0]; b[nq * 2][1] = t[1];
                b[nq * 2 + 1][0] = t[2]; b[nq * 2 + 1][1] = t[3];
            }

            #pragma unroll
            for (int mf = 0; mf < 2; mf++)
                #pragma unroll
                for (int nf = 0; nf < 8; nf++)
                    mma16816(acc[mf][nf], a[mf], b[nf]);
        }
    }

    // ---- epilogue: bias + activation, fp16 store to gate plane ----
    const int nch  = bn >> 10;                 // 0=Z(tanh), 1=F, 2=O (sigmoid)
    const int hoff = bn & 1023;
    __half* dst = (nch == 0) ? g_Z : (nch == 1) ? g_F : g_O;
    const float* bp = bias + bn + wn * 64;

    #pragma unroll
    for (int mf = 0; mf < 2; mf++) {
        const int r0 = bm + wm * 32 + mf * 16 + (lid >> 2);
        #pragma unroll
        for (int nf = 0; nf < 8; nf++) {
            const int col = nf * 8 + (lid & 3) * 2;
            const float b0 = __ldg(bp + col);
            const float b1 = __ldg(bp + col + 1);
            #pragma unroll
            for (int half = 0; half < 2; half++) {
                const int r = r0 + half * 8;
                float y0 = acc[mf][nf][2 * half + 0] + b0;
                float y1 = acc[mf][nf][2 * half + 1] + b1;
                float v0, v1;
                if (nch == 0) { v0 = fast_tanh(y0); v1 = fast_tanh(y1); }
                else          { v0 = fast_sigmoid(y0); v1 = fast_sigmoid(y1); }
                *(__half2*)&dst[(size_t)r * HDIM + hoff + wn * 64 + col] =
                    __floats2half2_rn(v0, v1);
            }
        }
    }
}

// ---------------------------------------------------------------------------
// Chunked scan over fp16 gates, 4 chains per thread (uint2 = 4 halves),
// 1024-block grids for DRAM occupancy.
// h_t = f_t*z_t + (1-f_t)*h_{t-1}
// ---------------------------------------------------------------------------
static __device__ __forceinline__ void unpack4(const uint2& u, float* f) {
    const __half2* h = (const __half2*)&u;
    float2 p0 = __half22float2(h[0]);
    float2 p1 = __half22float2(h[1]);
    f[0] = p0.x; f[1] = p0.y; f[2] = p1.x; f[3] = p1.y;
}

__global__ __launch_bounds__(256) void scan_chunks_kernel() {
    GDC_LAUNCH();
    GDC_WAIT();          // gemm's g_Z/g_F must be complete
    const int cg = blockIdx.x * 256 + threadIdx.x;   // 0..4095
    const int ck = blockIdx.y;
    const uint2* F4 = (const uint2*)g_F;
    const uint2* Z4 = (const uint2*)g_Z;
    size_t idx = (size_t)ck * CLEN * NCG4 + cg;
    float A[4], Bv[4];
    #pragma unroll
    for (int j = 0; j < 4; j++) { A[j] = 1.0f; Bv[j] = 0.0f; }
    #pragma unroll 4
    for (int s = 0; s < CLEN; s++, idx += NCG4) {
        float f[4], z[4];
        unpack4(F4[idx], f);
        unpack4(Z4[idx], z);
        #pragma unroll
        for (int j = 0; j < 4; j++) {
            Bv[j] = fmaf(f[j], z[j] - Bv[j], Bv[j]);
            A[j] *= (1.0f - f[j]);
        }
    }
    const size_t o = (size_t)ck * NCG4 + cg;
    ((float4*)g_cA)[o] = make_float4(A[0], A[1], A[2], A[3]);
    ((float4*)g_cB)[o] = make_float4(Bv[0], Bv[1], Bv[2], Bv[3]);
}

// One scalar chain per thread, batches of 16 with explicit register staging
// (32 independent loads in flight per thread); 128-thread blocks -> 128 blocks.
__global__ __launch_bounds__(128) void scan_combine_kernel() {
    GDC_LAUNCH();
    GDC_WAIT();          // chunks' g_cA/g_cB must be complete
    const int chain = blockIdx.x * 128 + threadIdx.x;   // 0..16383
    float h = 0.0f;
    for (int cb = 0; cb < NCHUNK; cb += 16) {
        float As[16], Bs[16];
        #pragma unroll
        for (int j = 0; j < 16; j++) {
            const size_t o = (size_t)(cb + j) * NCHAIN + chain;
            As[j] = g_cA[o];
            Bs[j] = g_cB[o];
        }
        #pragma unroll
        for (int j = 0; j < 16; j++) {
            g_cH[(size_t)(cb + j) * NCHAIN + chain] = h;
            h = fmaf(As[j], h, Bs[j]);
        }
    }
}

__global__ __launch_bounds__(256) void scan_final_kernel(float* __restrict__ out) {
    GDC_WAIT();          // combine's g_cH must be complete
    const int cg = blockIdx.x * 256 + threadIdx.x;   // 0..4095
    const int ck = blockIdx.y;
    const uint2* F4 = (const uint2*)g_F;
    const uint2* Z4 = (const uint2*)g_Z;
    const uint2* O4 = (const uint2*)g_O;
    float4* out4 = (float4*)out;
    size_t idx = (size_t)ck * CLEN * NCG4 + cg;
    float h[4];
    {
        const float4 h0 = ((const float4*)g_cH)[(size_t)ck * NCG4 + cg];
        h[0] = h0.x; h[1] = h0.y; h[2] = h0.z; h[3] = h0.w;
    }
    #pragma unroll 4
    for (int s = 0; s < CLEN; s++, idx += NCG4) {
        float f[4], z[4], o[4];
        unpack4(F4[idx], f);
        unpack4(Z4[idx], z);
        unpack4(O4[idx], o);
        float r[4];
        #pragma unroll
        for (int j = 0; j < 4; j++) {
            h[j] = fmaf(f[j], z[j] - h[j], h[j]);
            r[j] = o[j] * h[j];
        }
        out4[idx] = make_float4(r[0], r[1], r[2], r[3]);
    }
    if (ck == NCHUNK - 1)
        out4[(size_t)MDIM * HDIM / 4 + cg] = make_float4(h[0], h[1], h[2], h[3]);
}

// ---------------------------------------------------------------------------
// Host: launches with ProgrammaticStreamSerialization (PDL); falls back to a
// plain launch if the attributed launch is rejected (griddepcontrol.* are
// no-ops in that case).
// ---------------------------------------------------------------------------
static inline void launch_pdl(const void* fn, dim3 grid, dim3 block,
                              size_t smem, void** args) {
    cudaLaunchConfig_t cfg = {};
    cfg.gridDim = grid;
    cfg.blockDim = block;
    cfg.dynamicSmemBytes = smem;
    cfg.stream = 0;
    cudaLaunchAttribute at[1];
    at[0].id = cudaLaunchAttributeProgrammaticStreamSerialization;
    at[0].val.programmaticStreamSerializationAllowed = 1;
    cfg.attrs = at;
    cfg.numAttrs = 1;
    if (cudaLaunchKernelExC(&cfg, fn, args) != cudaSuccess) {
        cudaGetLastError();          // clear
        cfg.numAttrs = 0;
        cudaLaunchKernelExC(&cfg, fn, args);
    }
}

extern "C" void kernel_launch(void* const* d_in, const int* in_sizes, int n_in,
                              void* d_out, int out_size) {
    const float4* X4 = (const float4*)d_in[0];
    const float4* W4 = (const float4*)d_in[1];
    const float* bias = (const float*)d_in[2];
    float* out = (float*)d_out;

    cudaFuncSetAttribute(gemm_hmma_kernel,
                         cudaFuncAttributeMaxDynamicSharedMemorySize, GEMM_SMEM);

    {
        void* args[] = { (void*)&X4, (void*)&W4 };
        launch_pdl((const void*)conv_kernel,
                   dim3((NX4 + NW4) / 256), dim3(256), 0, args);
    }
    {
        void* args[] = { (void*)&bias };
        launch_pdl((const void*)gemm_hmma_kernel,
                   dim3(NDIM / BN, MDIM / BM), dim3(256), GEMM_SMEM, args);
    }
    {
        launch_pdl((const void*)scan_chunks_kernel,
                   dim3(NCG4 / 256, NCHUNK), dim3(256), 0, nullptr);
    }
    {
        launch_pdl((const void*)scan_combine_kernel,
                   dim3(NCHAIN / 128), dim3(128), 0, nullptr);
    }
    {
        void* args[] = { (void*)&out };
        launch_pdl((const void*)scan_final_kernel,
                   dim3(NCG4 / 256, NCHUNK), dim3(256), 0, args);
    }
}